// round 5
// baseline (speedup 1.0000x reference)
#include <cuda_runtime.h>
#include <math.h>
#include <stdint.h>

#define B_ 2
#define L_ 2048
#define H_ 8
#define D_ 64
#define F_ 5
#define KT 128
#define NT (L_/KT)
#define LUT_N 1024
#define DMAX 1.4143f
#define SMAX 12.0f

typedef unsigned long long ull;

__device__ float2 g_lut2[H_][LUT_N + 1];

// ---------------- LUT prep ----------------
__global__ void lut_kernel(const float* __restrict__ a, const float* __restrict__ b,
                           const float* __restrict__ c) {
    int h = blockIdx.y;
    int i = blockIdx.x * blockDim.x + threadIdx.x;
    if (i > LUT_N) return;
    float g[2];
#pragma unroll
    for (int t = 0; t < 2; t++) {
        float d = (float)(i + t) * (DMAX / (float)LUT_N);
        float s = 0.f;
#pragma unroll
        for (int f = 0; f < F_; f++) {
            float dt = d - c[h * F_ + f];
            s += a[h * F_ + f] * expf(-fabsf(b[h * F_ + f]) * dt * dt);
        }
        g[t] = s;
    }
    g_lut2[h][i] = make_float2(g[0], g[1]);
}

// ---------------- packed f32x2 helpers ----------------
__device__ __forceinline__ ull splat2(float x) {
    ull r; uint32_t u = __float_as_uint(x);
    asm("mov.b64 %0, {%1, %1};" : "=l"(r) : "r"(u));
    return r;
}
__device__ __forceinline__ float2 unpack2(ull v) {
    uint32_t lo, hi;
    asm("mov.b64 {%0, %1}, %2;" : "=r"(lo), "=r"(hi) : "l"(v));
    float2 f; f.x = __uint_as_float(lo); f.y = __uint_as_float(hi);
    return f;
}
#define FMA2ACC(S, A, Bv) \
    asm("fma.rn.f32x2 %0, %1, %2, %0;" : "+l"(S) : "l"(A), "l"(Bv))

// smem strides (floats)
#define DPQ 68
#define DPKT 132
#define DPV 68
#define DPP 132

// ---------------- main attention kernel ----------------
__global__ __launch_bounds__(256, 1)
void attn_kernel(const float* __restrict__ qs, const float* __restrict__ ks,
                 const float* __restrict__ vs, const float* __restrict__ qs_s,
                 const float* __restrict__ ks_s, float* __restrict__ out) {
    extern __shared__ float sm[];
    float* sQ  = sm;                      // [128][DPQ]   q rows x d
    float* sKT = sQ  + 128 * DPQ;         // [64][DPKT]   d rows x key cols (transposed)
    float* sV  = sKT + 64 * DPKT;         // [128][DPV]   key rows x d
    float* sP  = sV  + 128 * DPV;         // [128][DPP]   q rows x key cols
    float2* sLut = (float2*)(sP + 128 * DPP);   // LUT_N+1
    float* sQs0 = (float*)(sLut + (LUT_N + 1));
    float* sQs1 = sQs0 + 128;
    float* sKs0 = sQs1 + 128;
    float* sKs1 = sKs0 + 128;

    const int tid = threadIdx.x;
    const int tx = tid & 15, ty = tid >> 4;
    const int b = blockIdx.z, h = blockIdx.y;
    const int q0 = blockIdx.x * 128;
    const int lkey = tid & 127;           // loader: row (key or q)
    const int dh   = tid >> 7;            // loader: d half (0/1)

    for (int i = tid; i <= LUT_N; i += 256) sLut[i] = g_lut2[h][i];
    if (tid < 128) {
        float2 q2 = ((const float2*)qs_s)[b * L_ + q0 + tid];
        sQs0[tid] = q2.x; sQs1[tid] = q2.y;
    }
    // Q tile, scaled by 1/8
    {
        const float* gq = &qs[(((size_t)b * L_ + (q0 + lkey)) * H_ + h) * D_ + dh * 32];
#pragma unroll
        for (int i = 0; i < 8; i++) {
            float4 v = *(const float4*)(gq + i * 4);
            float4 w; w.x = v.x * 0.125f; w.y = v.y * 0.125f;
            w.z = v.z * 0.125f; w.w = v.w * 0.125f;
            *(float4*)&sQ[lkey * DPQ + dh * 32 + i * 4] = w;
        }
    }
    __syncthreads();

    float qx[8], qy[8];
#pragma unroll
    for (int i = 0; i < 8; i++) { qx[i] = sQs0[ty + 16 * i]; qy[i] = sQs1[ty + 16 * i]; }

    ull O2[8][2];
    float lp[8];
#pragma unroll
    for (int i = 0; i < 8; i++) { O2[i][0] = 0ull; O2[i][1] = 0ull; lp[i] = 0.f; }
    const float dscale = (float)LUT_N / DMAX;

    for (int t = 0; t < NT; t++) {
        const int k0 = t * KT;
        __syncthreads();   // prior PV done before overwriting sKT/sV/sKs

        // K tile -> transposed smem  sKT[d][key]
        {
            const float* gk = &ks[(((size_t)b * L_ + (k0 + lkey)) * H_ + h) * D_ + dh * 32];
#pragma unroll
            for (int i = 0; i < 8; i++) {
                float4 v = *(const float4*)(gk + i * 4);
                int d0 = dh * 32 + i * 4;
                sKT[(d0 + 0) * DPKT + lkey] = v.x;
                sKT[(d0 + 1) * DPKT + lkey] = v.y;
                sKT[(d0 + 2) * DPKT + lkey] = v.z;
                sKT[(d0 + 3) * DPKT + lkey] = v.w;
            }
        }
        // V tile (row-major)
        {
            const float* gv = &vs[(((size_t)b * L_ + (k0 + lkey)) * H_ + h) * D_ + dh * 32];
#pragma unroll
            for (int i = 0; i < 8; i++)
                *(float4*)&sV[lkey * DPV + dh * 32 + i * 4] = *(const float4*)(gv + i * 4);
        }
        if (tid < 128) {
            float2 k2 = ((const float2*)ks_s)[b * L_ + k0 + tid];
            sKs0[tid] = k2.x; sKs1[tid] = k2.y;
        }
        __syncthreads();

        // ---- S = Q@K^T via packed f32x2 ----
        // thread cols: 4tx+64j4+{0..3}; pairs p=0..3: (4tx+2p'), p' over {0,1,32,33}
        ull S2[8][4];
#pragma unroll
        for (int i = 0; i < 8; i++)
#pragma unroll
            for (int p = 0; p < 4; p++) S2[i][p] = 0ull;

#pragma unroll 2
        for (int kk = 0; kk < D_; kk += 4) {
            float4 qv[8];
#pragma unroll
            for (int i = 0; i < 8; i++)
                qv[i] = *(const float4*)&sQ[(ty + 16 * i) * DPQ + kk];
#pragma unroll
            for (int dk = 0; dk < 4; dk++) {
                ulonglong2 kv0 = *(const ulonglong2*)&sKT[(kk + dk) * DPKT + 4 * tx];
                ulonglong2 kv1 = *(const ulonglong2*)&sKT[(kk + dk) * DPKT + 4 * tx + 64];
#pragma unroll
                for (int i = 0; i < 8; i++) {
                    ull q2 = splat2(((const float*)&qv[i])[dk]);
                    FMA2ACC(S2[i][0], q2, kv0.x);
                    FMA2ACC(S2[i][1], q2, kv0.y);
                    FMA2ACC(S2[i][2], q2, kv1.x);
                    FMA2ACC(S2[i][3], q2, kv1.y);
                }
            }
        }

        // ---- bias + fixed-max exp + write P ----
        float kx[8], ky[8];
#pragma unroll
        for (int m = 0; m < 8; m++) {
            int col = 4 * tx + (m >> 2) * 64 + (m & 3);
            kx[m] = sKs0[col]; ky[m] = sKs1[col];
        }
#pragma unroll
        for (int i = 0; i < 8; i++) {
            float e[8];
#pragma unroll
            for (int p = 0; p < 4; p++) {
                float2 sv = unpack2(S2[i][p]);
#pragma unroll
                for (int bb = 0; bb < 2; bb++) {
                    int m = ((p & 1) * 2 + bb) + (p >> 1) * 4;   // 0..7 within kx/ky
                    float dx = qx[i] - kx[m], dy = qy[i] - ky[m];
                    float dd;
                    asm("sqrt.approx.f32 %0, %1;" : "=f"(dd) : "f"(fmaf(dx, dx, dy * dy)));
                    float tt = fminf(dd * dscale, (float)LUT_N - 0.001f);
                    int ii = (int)tt;
                    float fr = tt - (float)ii;
                    float2 g = sLut[ii];
                    float s = ((bb == 0) ? sv.x : sv.y) + g.x + fr * (g.y - g.x);
                    float pe = __expf(s - SMAX);
                    lp[i] += pe;
                    e[m] = pe;
                }
            }
            float4 w0 = make_float4(e[0], e[1], e[2], e[3]);
            float4 w1 = make_float4(e[4], e[5], e[6], e[7]);
            *(float4*)&sP[(ty + 16 * i) * DPP + 4 * tx]      = w0;
            *(float4*)&sP[(ty + 16 * i) * DPP + 4 * tx + 64] = w1;
        }
        __syncthreads();

        // ---- O += P @ V via packed f32x2 (pairs over d) ----
#pragma unroll 2
        for (int kk = 0; kk < KT; kk += 4) {
            float4 pv[8];
#pragma unroll
            for (int i = 0; i < 8; i++)
                pv[i] = *(const float4*)&sP[(ty + 16 * i) * DPP + kk];
#pragma unroll
            for (int dk = 0; dk < 4; dk++) {
                ulonglong2 vv = *(const ulonglong2*)&sV[(kk + dk) * DPV + 4 * tx];
#pragma unroll
                for (int i = 0; i < 8; i++) {
                    ull p2 = splat2(((const float*)&pv[i])[dk]);
                    FMA2ACC(O2[i][0], p2, vv.x);
                    FMA2ACC(O2[i][1], p2, vv.y);
                }
            }
        }
    }

    // ---- finalize ----
#pragma unroll
    for (int i = 0; i < 8; i++) {
#pragma unroll
        for (int off = 8; off > 0; off >>= 1)
            lp[i] += __shfl_xor_sync(0xffffffffu, lp[i], off);
        float linv = 1.0f / lp[i];
        float2 oa = unpack2(O2[i][0]);
        float2 ob = unpack2(O2[i][1]);
        float4 o4;
        o4.x = oa.x * linv; o4.y = oa.y * linv;
        o4.z = ob.x * linv; o4.w = ob.y * linv;
        *(float4*)&out[(((size_t)b * L_ + (q0 + ty + 16 * i)) * H_ + h) * D_ + 4 * tx] = o4;
    }
}

static const int SMEM_BYTES =
    (128 * DPQ + 64 * DPKT + 128 * DPV + 128 * DPP + 2 * (LUT_N + 1) + 4 * 128)
    * (int)sizeof(float);

extern "C" void kernel_launch(void* const* d_in, const int* in_sizes, int n_in,
                              void* d_out, int out_size) {
    const float* qs   = (const float*)d_in[0];
    const float* ks   = (const float*)d_in[1];
    const float* vs   = (const float*)d_in[2];
    const float* qs_s = (const float*)d_in[3];
    const float* ks_s = (const float*)d_in[4];
    const float* a    = (const float*)d_in[5];
    const float* b    = (const float*)d_in[6];
    const float* c    = (const float*)d_in[7];
    float* out = (float*)d_out;

    lut_kernel<<<dim3((LUT_N + 128) / 128, H_), 128>>>(a, b, c);

    cudaFuncSetAttribute(attn_kernel,
                         cudaFuncAttributeMaxDynamicSharedMemorySize, SMEM_BYTES);
    attn_kernel<<<dim3(L_ / 128, H_, B_), 256, SMEM_BYTES>>>(
        qs, ks, vs, qs_s, ks_s, out);
}

// round 6
// speedup vs baseline: 2.3786x; 2.3786x over previous
#include <cuda_runtime.h>
#include <cuda_bf16.h>
#include <math.h>
#include <stdint.h>

#define B_ 2
#define L_ 2048
#define H_ 8
#define D_ 64
#define F_ 5
#define KT 128
#define NT (L_/KT)
#define LUT_N 1024
#define DMAX 1.4143f
#define SMAX 12.0f

// bf16 hi/lo split K and V, layout [b*H+h][l][d]
__device__ __nv_bfloat16 g_khi[B_*H_*L_*D_];
__device__ __nv_bfloat16 g_klo[B_*H_*L_*D_];
__device__ __nv_bfloat16 g_vhi[B_*H_*L_*D_];
__device__ __nv_bfloat16 g_vlo[B_*H_*L_*D_];
__device__ float2 g_lut2[H_][LUT_N + 1];

// ---------------- smem layout (bytes) ----------------
// rows of K/V/Q tiles are 72 halves = 144 B (ldmatrix conflict-free)
#define STRB   144
#define SM_LUT 0                 // float2[1025] = 8200 -> pad 8320
#define SM_KS  8320              // float2[2][128] = 2048
#define SM_Q   10368             // QHI 18432 | QLO 18432
#define SM_KB  47232             // buf b at +b*36864: KHI 18432 | KLO 18432
#define SM_VB  120960            // buf b at +b*36864: VHI | VLO
#define SMEM_TOTAL 194688

__device__ __forceinline__ uint32_t s2u(const void* p) {
    uint32_t a;
    asm("{ .reg .u64 t; cvta.to.shared.u64 t, %1; cvt.u32.u64 %0, t; }"
        : "=r"(a) : "l"(p));
    return a;
}

#define CP16(dst, src) \
    asm volatile("cp.async.cg.shared.global [%0], [%1], 16;" :: "r"(dst), "l"(src))
#define CPCOMMIT() asm volatile("cp.async.commit_group;" ::: "memory")
#define CPWAIT(n)  asm volatile("cp.async.wait_group %0;" :: "n"(n) : "memory")

#define LDSM4(R, addr) \
    asm volatile("ldmatrix.sync.aligned.m8n8.x4.shared.b16 {%0,%1,%2,%3}, [%4];" \
        : "=r"((R)[0]), "=r"((R)[1]), "=r"((R)[2]), "=r"((R)[3]) : "r"(addr))
#define LDSM4T(R, addr) \
    asm volatile("ldmatrix.sync.aligned.m8n8.x4.trans.shared.b16 {%0,%1,%2,%3}, [%4];" \
        : "=r"((R)[0]), "=r"((R)[1]), "=r"((R)[2]), "=r"((R)[3]) : "r"(addr))

#define MMA16816(C, A, b0, b1) \
    asm volatile("mma.sync.aligned.m16n8k16.row.col.f32.bf16.bf16.f32 " \
        "{%0,%1,%2,%3}, {%4,%5,%6,%7}, {%8,%9}, {%0,%1,%2,%3};" \
        : "+f"((C)[0]), "+f"((C)[1]), "+f"((C)[2]), "+f"((C)[3]) \
        : "r"((A)[0]), "r"((A)[1]), "r"((A)[2]), "r"((A)[3]), "r"(b0), "r"(b1))

// cvt.rn.bf16x2.f32 d, x, y  ->  d.high = bf16(x), d.low = bf16(y)
__device__ __forceinline__ uint32_t packbf(float hi, float lo) {
    uint32_t r;
    asm("cvt.rn.bf16x2.f32 %0, %1, %2;" : "=r"(r) : "f"(hi), "f"(lo));
    return r;
}
// split two f32 into (hi bf16x2, lo bf16x2) residual pair
__device__ __forceinline__ void split2(float x0, float x1, uint32_t& h, uint32_t& l) {
    h = packbf(x1, x0);
    float f0 = __uint_as_float(h << 16);
    float f1 = __uint_as_float(h & 0xffff0000u);
    l = packbf(x1 - f1, x0 - f0);
}

// ---------------- prep: split K,V into bf16 hi/lo [bh][l][d] ----------------
__global__ void prep_kernel(const float4* __restrict__ ks, const float4* __restrict__ vs) {
    int i = blockIdx.x * blockDim.x + threadIdx.x;   // over B*H*L*D/4
    if (i >= B_ * H_ * L_ * D_ / 4) return;
    int d4 = i & 15, h = (i >> 4) & 7, l = (i >> 7) & 2047, b = i >> 18;
    int dst = (((b * H_ + h) * L_ + l) * D_) / 4 + d4;   // uint2 units
    float4 kv = ks[i];
    uint32_t h0, h1, l0, l1;
    split2(kv.x, kv.y, h0, l0);
    split2(kv.z, kv.w, h1, l1);
    ((uint2*)g_khi)[dst] = make_uint2(h0, h1);
    ((uint2*)g_klo)[dst] = make_uint2(l0, l1);
    float4 vv = vs[i];
    split2(vv.x, vv.y, h0, l0);
    split2(vv.z, vv.w, h1, l1);
    ((uint2*)g_vhi)[dst] = make_uint2(h0, h1);
    ((uint2*)g_vlo)[dst] = make_uint2(l0, l1);
}

__global__ void lut_kernel(const float* __restrict__ a, const float* __restrict__ b,
                           const float* __restrict__ c) {
    int h = blockIdx.y;
    int i = blockIdx.x * blockDim.x + threadIdx.x;
    if (i > LUT_N) return;
    float g[2];
#pragma unroll
    for (int t = 0; t < 2; t++) {
        float d = (float)(i + t) * (DMAX / (float)LUT_N);
        float s = 0.f;
#pragma unroll
        for (int f = 0; f < F_; f++) {
            float dt = d - c[h * F_ + f];
            s += a[h * F_ + f] * expf(-fabsf(b[h * F_ + f]) * dt * dt);
        }
        g[t] = s;
    }
    g_lut2[h][i] = make_float2(g[0], g[1]);
}

// ---------------- main attention kernel ----------------
__global__ __launch_bounds__(256, 1)
void attn_kernel(const float* __restrict__ qs, const float* __restrict__ qs_s,
                 const float* __restrict__ ks_s, float* __restrict__ out) {
    extern __shared__ char smem[];
    const uint32_t sb = s2u(smem);
    const int tid = threadIdx.x;
    const int w = tid >> 5, lane = tid & 31;
    const int gid = lane >> 2, tig = lane & 3;
    const int b = blockIdx.z, h = blockIdx.y;
    const int q0 = blockIdx.x * 128;
    const int bh = b * H_ + h;

    const char* gkh = (const char*)g_khi + (size_t)bh * L_ * D_ * 2;
    const char* gkl = (const char*)g_klo + (size_t)bh * L_ * D_ * 2;
    const char* gvh = (const char*)g_vhi + (size_t)bh * L_ * D_ * 2;
    const char* gvl = (const char*)g_vlo + (size_t)bh * L_ * D_ * 2;

    const int cr = tid >> 3, cs = tid & 7;  // cp.async: row base, 16B segment

    // ---- issue tile t into buffer bsel (cp.async) + ks scalars ----
#define ISSUE_TILE(t, bsel) do {                                               \
    int _k0 = (t) * KT;                                                        \
    uint32_t _kd = sb + SM_KB + (bsel) * 36864 + cs * 16;                      \
    uint32_t _vd = sb + SM_VB + (bsel) * 36864 + cs * 16;                      \
    _Pragma("unroll")                                                          \
    for (int _r = 0; _r < 4; _r++) {                                           \
        int rr = cr + _r * 32;                                                 \
        size_t so = (size_t)(_k0 + rr) * 128 + cs * 16;                        \
        CP16(_kd + rr * STRB,         gkh + so);                               \
        CP16(_kd + 18432 + rr * STRB, gkl + so);                               \
        CP16(_vd + rr * STRB,         gvh + so);                               \
        CP16(_vd + 18432 + rr * STRB, gvl + so);                               \
    }                                                                          \
    if (tid < 128)                                                             \
        *(float2*)(smem + SM_KS + (bsel) * 1024 + tid * 8) =                   \
            ((const float2*)ks_s)[b * L_ + _k0 + tid];                         \
} while (0)

    // prologue: start tile 0, stage LUT + Q
    ISSUE_TILE(0, 0);
    CPCOMMIT();

    float2* sLut = (float2*)(smem + SM_LUT);
    for (int i = tid; i <= LUT_N; i += 256) sLut[i] = g_lut2[h][i];

    {   // Q: load f32, scale 1/8, split bf16 hi/lo into smem
        int r = tid >> 1, dq = (tid & 1) * 32;
        const float4* gq = (const float4*)(qs + (((size_t)b * L_ + q0 + r) * H_ + h) * D_ + dq);
#pragma unroll
        for (int i = 0; i < 8; i++) {
            float4 v = gq[i];
            v.x *= 0.125f; v.y *= 0.125f; v.z *= 0.125f; v.w *= 0.125f;
            uint32_t h0, h1, l0, l1;
            split2(v.x, v.y, h0, l0);
            split2(v.z, v.w, h1, l1);
            int off = r * STRB + dq * 2 + i * 8;
            *(uint2*)(smem + SM_Q + off)         = make_uint2(h0, h1);
            *(uint2*)(smem + SM_Q + 18432 + off) = make_uint2(l0, l1);
        }
    }
    __syncthreads();

    // Q fragments (resident in registers for whole kernel)
    uint32_t qh[4][4], ql[4][4];
    {
        uint32_t qa = sb + SM_Q + (16 * w + ((lane & 7) + ((lane >> 3) & 1) * 8)) * STRB
                    + ((lane >> 4) & 1) * 16;
#pragma unroll
        for (int kt = 0; kt < 4; kt++) {
            LDSM4(qh[kt], qa + kt * 32);
            LDSM4(ql[kt], qa + 18432 + kt * 32);
        }
    }

    // per-lane q scan scalars (rows rA = 16w+gid, rB = rA+8)
    const float2 qsA = ((const float2*)qs_s)[b * L_ + q0 + 16 * w + gid];
    const float2 qsB = ((const float2*)qs_s)[b * L_ + q0 + 16 * w + gid + 8];
    const float dscale = (float)LUT_N / DMAX;

    // lane bases for ldmatrix of K (non-trans) and V (trans)
    const uint32_t klane = ((lane & 7) + ((lane >> 4) & 1) * 8) * STRB + ((lane >> 3) & 1) * 16;
    const uint32_t vlane = ((lane & 7) + ((lane >> 3) & 1) * 8) * STRB + ((lane >> 4) & 1) * 16;

    float O[8][4];
#pragma unroll
    for (int n = 0; n < 8; n++)
#pragma unroll
        for (int c = 0; c < 4; c++) O[n][c] = 0.f;
    float lpA = 0.f, lpB = 0.f;

    for (int t = 0; t < NT; t++) {
        const int buf = t & 1;
        if (t + 1 < NT) { ISSUE_TILE(t + 1, buf ^ 1); CPCOMMIT(); }
        if (t + 1 < NT) { CPWAIT(1); } else { CPWAIT(0); }
        __syncthreads();

        // ---- QK: S[16 ntiles][4] ----
        float S[16][4];
#pragma unroll
        for (int j = 0; j < 16; j++)
#pragma unroll
            for (int c = 0; c < 4; c++) S[j][c] = 0.f;

        const uint32_t kb = sb + SM_KB + buf * 36864 + klane;
#pragma unroll
        for (int jp = 0; jp < 8; jp++) {
#pragma unroll
            for (int kt = 0; kt < 4; kt++) {
                uint32_t khf[4], klf[4];
                LDSM4(khf, kb + jp * (16 * STRB) + kt * 32);
                LDSM4(klf, kb + 18432 + jp * (16 * STRB) + kt * 32);
                MMA16816(S[2 * jp],     qh[kt], khf[0], khf[1]);
                MMA16816(S[2 * jp],     ql[kt], khf[0], khf[1]);
                MMA16816(S[2 * jp],     qh[kt], klf[0], klf[1]);
                MMA16816(S[2 * jp + 1], qh[kt], khf[2], khf[3]);
                MMA16816(S[2 * jp + 1], ql[kt], khf[2], khf[3]);
                MMA16816(S[2 * jp + 1], qh[kt], klf[2], klf[3]);
            }
        }

        // ---- epilogue + PV in two halves (register pressure) ----
        const uint32_t vb = sb + SM_VB + buf * 36864 + vlane;
        const char* ksb = smem + SM_KS + buf * 1024;

#pragma unroll
        for (int half = 0; half < 2; half++) {
            uint32_t PH[4][4], PL[4][4];
#pragma unroll
            for (int jj = 0; jj < 8; jj++) {
                int j = half * 8 + jj;
                int col = 8 * j + 2 * tig;
                float2 k0 = *(const float2*)(ksb + col * 8);
                float2 k1 = *(const float2*)(ksb + col * 8 + 8);
                float p[4];
#pragma unroll
                for (int e = 0; e < 4; e++) {
                    float2 qq = (e < 2) ? qsA : qsB;
                    float2 kk = (e & 1) ? k1 : k0;
                    float dx = qq.x - kk.x, dy = qq.y - kk.y;
                    float dd;
                    asm("sqrt.approx.f32 %0, %1;" : "=f"(dd) : "f"(fmaf(dx, dx, dy * dy)));
                    float tt = fminf(dd * dscale, (float)LUT_N - 0.001f);
                    int ii = (int)tt;
                    float fr = tt - (float)ii;
                    float2 g = sLut[ii];
                    float s = S[j][e] + g.x + fr * (g.y - g.x);
                    p[e] = __expf(s - SMAX);
                }
                lpA += p[0] + p[1];
                lpB += p[2] + p[3];
                int m = jj >> 1, slot = (jj & 1) * 2;
                split2(p[0], p[1], PH[m][slot],     PL[m][slot]);
                split2(p[2], p[3], PH[m][slot + 1], PL[m][slot + 1]);
            }
            // PV for ktiles m = half*4 .. half*4+3
#pragma unroll
            for (int mm = 0; mm < 4; mm++) {
                int m = half * 4 + mm;
#pragma unroll
                for (int np = 0; np < 4; np++) {
                    uint32_t vhf[4], vlf[4];
                    LDSM4T(vhf, vb + m * (16 * STRB) + np * 32);
                    LDSM4T(vlf, vb + 18432 + m * (16 * STRB) + np * 32);
                    MMA16816(O[2 * np],     PH[mm], vhf[0], vhf[1]);
                    MMA16816(O[2 * np],     PL[mm], vhf[0], vhf[1]);
                    MMA16816(O[2 * np],     PH[mm], vlf[0], vlf[1]);
                    MMA16816(O[2 * np + 1], PH[mm], vhf[2], vhf[3]);
                    MMA16816(O[2 * np + 1], PL[mm], vhf[2], vhf[3]);
                    MMA16816(O[2 * np + 1], PH[mm], vlf[2], vlf[3]);
                }
            }
        }
        __syncthreads();
    }

    // ---- finalize: reduce row sums over the 4 tig lanes, normalize, store ----
    lpA += __shfl_xor_sync(0xffffffffu, lpA, 1);
    lpA += __shfl_xor_sync(0xffffffffu, lpA, 2);
    lpB += __shfl_xor_sync(0xffffffffu, lpB, 1);
    lpB += __shfl_xor_sync(0xffffffffu, lpB, 2);
    float invA = 1.0f / lpA, invB = 1.0f / lpB;

    int rA = q0 + 16 * w + gid;
    float* outA = &out[(((size_t)b * L_ + rA) * H_ + h) * D_ + 2 * tig];
    float* outB = &out[(((size_t)b * L_ + rA + 8) * H_ + h) * D_ + 2 * tig];
#pragma unroll
    for (int n = 0; n < 8; n++) {
        *(float2*)(outA + 8 * n) = make_float2(O[n][0] * invA, O[n][1] * invA);
        *(float2*)(outB + 8 * n) = make_float2(O[n][2] * invB, O[n][3] * invB);
    }
}

extern "C" void kernel_launch(void* const* d_in, const int* in_sizes, int n_in,
                              void* d_out, int out_size) {
    const float* qs   = (const float*)d_in[0];
    const float* ks   = (const float*)d_in[1];
    const float* vs   = (const float*)d_in[2];
    const float* qs_s = (const float*)d_in[3];
    const float* ks_s = (const float*)d_in[4];
    const float* a    = (const float*)d_in[5];
    const float* b    = (const float*)d_in[6];
    const float* c    = (const float*)d_in[7];
    float* out = (float*)d_out;

    prep_kernel<<<(B_ * H_ * L_ * D_ / 4 + 255) / 256, 256>>>(
        (const float4*)ks, (const float4*)vs);
    lut_kernel<<<dim3((LUT_N + 128) / 128, H_), 128>>>(a, b, c);

    cudaFuncSetAttribute(attn_kernel,
                         cudaFuncAttributeMaxDynamicSharedMemorySize, SMEM_TOTAL);
    attn_kernel<<<dim3(L_ / 128, H_, B_), 256, SMEM_TOTAL>>>(qs, qs_s, ks_s, out);
}

// round 7
// speedup vs baseline: 2.4235x; 1.0189x over previous
#include <cuda_runtime.h>
#include <cuda_bf16.h>
#include <math.h>
#include <stdint.h>

#define B_ 2
#define L_ 2048
#define H_ 8
#define D_ 64
#define F_ 5
#define KT 64
#define NT (L_/KT)
#define LUT_N 1024
#define DMAX 1.4143f
#define SMAX 12.0f

// bf16 hi/lo split K and V, layout [b*H+h][l][d]
__device__ __nv_bfloat16 g_khi[B_*H_*L_*D_];
__device__ __nv_bfloat16 g_klo[B_*H_*L_*D_];
__device__ __nv_bfloat16 g_vhi[B_*H_*L_*D_];
__device__ __nv_bfloat16 g_vlo[B_*H_*L_*D_];
__device__ float2 g_lut2[H_][LUT_N + 1];

// ---------------- smem layout (bytes) ----------------
// K/V tile rows: 64 halves used, stride 144 B (ldmatrix conflict-free)
#define STRB    144
#define SM_LUT  0                // float2[1025] = 8200 -> pad 8320
#define SM_KS   8320             // float2[2][64] = 1024
#define SM_KV   9344             // buf b at +b*36864: KHI | KLO(+9216) | VHI(+18432) | VLO(+27648)
#define SM_QSTG (SM_KV + 36864)  // aliases buf1: QHI 18432 | QLO 18432
#define SMEM_TOTAL (SM_KV + 2*36864)   // 83072 B -> 2 CTAs/SM

__device__ __forceinline__ uint32_t s2u(const void* p) {
    uint32_t a;
    asm("{ .reg .u64 t; cvta.to.shared.u64 t, %1; cvt.u32.u64 %0, t; }"
        : "=r"(a) : "l"(p));
    return a;
}

#define CP16(dst, src) \
    asm volatile("cp.async.cg.shared.global [%0], [%1], 16;" :: "r"(dst), "l"(src))
#define CPCOMMIT() asm volatile("cp.async.commit_group;" ::: "memory")
#define CPWAIT(n)  asm volatile("cp.async.wait_group %0;" :: "n"(n) : "memory")

#define LDSM4(R, addr) \
    asm volatile("ldmatrix.sync.aligned.m8n8.x4.shared.b16 {%0,%1,%2,%3}, [%4];" \
        : "=r"((R)[0]), "=r"((R)[1]), "=r"((R)[2]), "=r"((R)[3]) : "r"(addr))
#define LDSM4T(R, addr) \
    asm volatile("ldmatrix.sync.aligned.m8n8.x4.trans.shared.b16 {%0,%1,%2,%3}, [%4];" \
        : "=r"((R)[0]), "=r"((R)[1]), "=r"((R)[2]), "=r"((R)[3]) : "r"(addr))

#define MMA16816(C, A, b0, b1) \
    asm volatile("mma.sync.aligned.m16n8k16.row.col.f32.bf16.bf16.f32 " \
        "{%0,%1,%2,%3}, {%4,%5,%6,%7}, {%8,%9}, {%0,%1,%2,%3};" \
        : "+f"((C)[0]), "+f"((C)[1]), "+f"((C)[2]), "+f"((C)[3]) \
        : "r"((A)[0]), "r"((A)[1]), "r"((A)[2]), "r"((A)[3]), "r"(b0), "r"(b1))

__device__ __forceinline__ uint32_t packbf(float hi, float lo) {
    uint32_t r;
    asm("cvt.rn.bf16x2.f32 %0, %1, %2;" : "=r"(r) : "f"(hi), "f"(lo));
    return r;
}
__device__ __forceinline__ void split2(float x0, float x1, uint32_t& h, uint32_t& l) {
    h = packbf(x1, x0);
    float f0 = __uint_as_float(h << 16);
    float f1 = __uint_as_float(h & 0xffff0000u);
    l = packbf(x1 - f1, x0 - f0);
}

// ---------------- prep: split K,V into bf16 hi/lo [bh][l][d] ----------------
__global__ void prep_kernel(const float4* __restrict__ ks, const float4* __restrict__ vs) {
    int i = blockIdx.x * blockDim.x + threadIdx.x;
    if (i >= B_ * H_ * L_ * D_ / 4) return;
    int d4 = i & 15, h = (i >> 4) & 7, l = (i >> 7) & 2047, b = i >> 18;
    int dst = (((b * H_ + h) * L_ + l) * D_) / 4 + d4;
    float4 kv = ks[i];
    uint32_t h0, h1, l0, l1;
    split2(kv.x, kv.y, h0, l0);
    split2(kv.z, kv.w, h1, l1);
    ((uint2*)g_khi)[dst] = make_uint2(h0, h1);
    ((uint2*)g_klo)[dst] = make_uint2(l0, l1);
    float4 vv = vs[i];
    split2(vv.x, vv.y, h0, l0);
    split2(vv.z, vv.w, h1, l1);
    ((uint2*)g_vhi)[dst] = make_uint2(h0, h1);
    ((uint2*)g_vlo)[dst] = make_uint2(l0, l1);
}

__global__ void lut_kernel(const float* __restrict__ a, const float* __restrict__ b,
                           const float* __restrict__ c) {
    int h = blockIdx.y;
    int i = blockIdx.x * blockDim.x + threadIdx.x;
    if (i > LUT_N) return;
    float g[2];
#pragma unroll
    for (int t = 0; t < 2; t++) {
        float d = (float)(i + t) * (DMAX / (float)LUT_N);
        float s = 0.f;
#pragma unroll
        for (int f = 0; f < F_; f++) {
            float dt = d - c[h * F_ + f];
            s += a[h * F_ + f] * expf(-fabsf(b[h * F_ + f]) * dt * dt);
        }
        g[t] = s;
    }
    g_lut2[h][i] = make_float2(g[0], g[1]);
}

// ---------------- main attention kernel ----------------
__global__ __launch_bounds__(256, 2)
void attn_kernel(const float* __restrict__ qs, const float* __restrict__ qs_s,
                 const float* __restrict__ ks_s, float* __restrict__ out) {
    extern __shared__ char smem[];
    const uint32_t sb = s2u(smem);
    const int tid = threadIdx.x;
    const int w = tid >> 5, lane = tid & 31;
    const int gid = lane >> 2, tig = lane & 3;
    const int b = blockIdx.z, h = blockIdx.y;
    const int q0 = blockIdx.x * 128;
    const int bh = b * H_ + h;

    const char* gkh = (const char*)g_khi + (size_t)bh * L_ * D_ * 2;
    const char* gkl = (const char*)g_klo + (size_t)bh * L_ * D_ * 2;
    const char* gvh = (const char*)g_vhi + (size_t)bh * L_ * D_ * 2;
    const char* gvl = (const char*)g_vlo + (size_t)bh * L_ * D_ * 2;

    const int cr = tid >> 3, cs = tid & 7;  // cp.async: row base 0..31, 16B seg

    // issue tile t (64 rows) into buffer bsel
#define ISSUE_TILE(t, bsel) do {                                               \
    int _k0 = (t) * KT;                                                        \
    uint32_t _dd = sb + SM_KV + (bsel) * 36864 + cs * 16;                      \
    _Pragma("unroll")                                                          \
    for (int _r = 0; _r < 2; _r++) {                                           \
        int rr = cr + _r * 32;                                                 \
        size_t so = (size_t)(_k0 + rr) * 128 + cs * 16;                        \
        CP16(_dd + rr * STRB,         gkh + so);                               \
        CP16(_dd + 9216  + rr * STRB, gkl + so);                               \
        CP16(_dd + 18432 + rr * STRB, gvh + so);                               \
        CP16(_dd + 27648 + rr * STRB, gvl + so);                               \
    }                                                                          \
    if (tid < 64)                                                              \
        *(float2*)(smem + SM_KS + (bsel) * 512 + tid * 8) =                    \
            ((const float2*)ks_s)[b * L_ + _k0 + tid];                         \
} while (0)

    // prologue: start tile 0 into buf0; stage LUT + Q (into buf1 alias)
    ISSUE_TILE(0, 0);
    CPCOMMIT();

    float2* sLut = (float2*)(smem + SM_LUT);
    for (int i = tid; i <= LUT_N; i += 256) sLut[i] = g_lut2[h][i];

    {   // Q: load f32, scale 1/8, split bf16 hi/lo into QSTG
        int r = tid >> 1, dq = (tid & 1) * 32;
        const float4* gq = (const float4*)(qs + (((size_t)b * L_ + q0 + r) * H_ + h) * D_ + dq);
#pragma unroll
        for (int i = 0; i < 8; i++) {
            float4 v = gq[i];
            v.x *= 0.125f; v.y *= 0.125f; v.z *= 0.125f; v.w *= 0.125f;
            uint32_t h0, h1, l0, l1;
            split2(v.x, v.y, h0, l0);
            split2(v.z, v.w, h1, l1);
            int off = r * STRB + dq * 2 + i * 8;
            *(uint2*)(smem + SM_QSTG + off)         = make_uint2(h0, h1);
            *(uint2*)(smem + SM_QSTG + 18432 + off) = make_uint2(l0, l1);
        }
    }
    __syncthreads();

    // Q fragments (register-resident)
    uint32_t qh[4][4], ql[4][4];
    {
        uint32_t qa = sb + SM_QSTG + (16 * w + ((lane & 7) + ((lane >> 3) & 1) * 8)) * STRB
                    + ((lane >> 4) & 1) * 16;
#pragma unroll
        for (int kt = 0; kt < 4; kt++) {
            LDSM4(qh[kt], qa + kt * 32);
            LDSM4(ql[kt], qa + 18432 + kt * 32);
        }
    }
    __syncthreads();   // Q region free -> may become buf1

    const float2 qsA = ((const float2*)qs_s)[b * L_ + q0 + 16 * w + gid];
    const float2 qsB = ((const float2*)qs_s)[b * L_ + q0 + 16 * w + gid + 8];
    const float dscale = (float)LUT_N / DMAX;

    const uint32_t klane = ((lane & 7) + ((lane >> 4) & 1) * 8) * STRB + ((lane >> 3) & 1) * 16;
    const uint32_t vlane = ((lane & 7) + ((lane >> 3) & 1) * 8) * STRB + ((lane >> 4) & 1) * 16;

    float O[8][4];
#pragma unroll
    for (int n = 0; n < 8; n++)
#pragma unroll
        for (int c = 0; c < 4; c++) O[n][c] = 0.f;
    float lpA = 0.f, lpB = 0.f;

    for (int t = 0; t < NT; t++) {
        const int buf = t & 1;
        if (t + 1 < NT) { ISSUE_TILE(t + 1, buf ^ 1); CPCOMMIT(); }
        if (t + 1 < NT) { CPWAIT(1); } else { CPWAIT(0); }
        __syncthreads();

        // ---- QK: S[8][4] over warp's 16 q-rows x 64 k-cols ----
        float S[8][4];
#pragma unroll
        for (int j = 0; j < 8; j++)
#pragma unroll
            for (int c = 0; c < 4; c++) S[j][c] = 0.f;

        const uint32_t kb = sb + SM_KV + buf * 36864 + klane;
#pragma unroll
        for (int jp = 0; jp < 4; jp++) {
#pragma unroll
            for (int kt = 0; kt < 4; kt++) {
                uint32_t khf[4], klf[4];
                LDSM4(khf, kb + jp * (16 * STRB) + kt * 32);
                LDSM4(klf, kb + 9216 + jp * (16 * STRB) + kt * 32);
                MMA16816(S[2 * jp],     qh[kt], khf[0], khf[1]);
                MMA16816(S[2 * jp],     ql[kt], khf[0], khf[1]);
                MMA16816(S[2 * jp],     qh[kt], klf[0], klf[1]);
                MMA16816(S[2 * jp + 1], qh[kt], khf[2], khf[3]);
                MMA16816(S[2 * jp + 1], ql[kt], khf[2], khf[3]);
                MMA16816(S[2 * jp + 1], qh[kt], klf[2], klf[3]);
            }
        }

        // ---- epilogue: bias + fixed-max exp + pack P fragments ----
        const char* ksb = smem + SM_KS + buf * 512;
        uint32_t PH[4][4], PL[4][4];
#pragma unroll
        for (int j = 0; j < 8; j++) {
            int col = 8 * j + 2 * tig;
            float2 k0 = *(const float2*)(ksb + col * 8);
            float2 k1 = *(const float2*)(ksb + col * 8 + 8);
            float p[4];
#pragma unroll
            for (int e = 0; e < 4; e++) {
                float2 qq = (e < 2) ? qsA : qsB;
                float2 kk = (e & 1) ? k1 : k0;
                float dx = qq.x - kk.x, dy = qq.y - kk.y;
                float dd;
                asm("sqrt.approx.f32 %0, %1;" : "=f"(dd) : "f"(fmaf(dx, dx, dy * dy)));
                float tt = fminf(dd * dscale, (float)LUT_N - 0.001f);
                int ii = (int)tt;
                float fr = tt - (float)ii;
                float2 g = sLut[ii];
                float s = S[j][e] + g.x + fr * (g.y - g.x);
                p[e] = __expf(s - SMAX);
            }
            lpA += p[0] + p[1];
            lpB += p[2] + p[3];
            int m = j >> 1, slot = (j & 1) * 2;
            split2(p[0], p[1], PH[m][slot],     PL[m][slot]);
            split2(p[2], p[3], PH[m][slot + 1], PL[m][slot + 1]);
        }

        // ---- PV: O += P(16x64) @ V(64x64) ----
        const uint32_t vb = sb + SM_KV + buf * 36864 + 18432 + vlane;
#pragma unroll
        for (int m = 0; m < 4; m++) {
#pragma unroll
            for (int np = 0; np < 4; np++) {
                uint32_t vhf[4], vlf[4];
                LDSM4T(vhf, vb + m * (16 * STRB) + np * 32);
                LDSM4T(vlf, vb + 9216 + m * (16 * STRB) + np * 32);
                MMA16816(O[2 * np],     PH[m], vhf[0], vhf[1]);
                MMA16816(O[2 * np],     PL[m], vhf[0], vhf[1]);
                MMA16816(O[2 * np],     PH[m], vlf[0], vlf[1]);
                MMA16816(O[2 * np + 1], PH[m], vhf[2], vhf[3]);
                MMA16816(O[2 * np + 1], PL[m], vhf[2], vhf[3]);
                MMA16816(O[2 * np + 1], PH[m], vlf[2], vlf[3]);
            }
        }
        __syncthreads();
    }

    // ---- finalize ----
    lpA += __shfl_xor_sync(0xffffffffu, lpA, 1);
    lpA += __shfl_xor_sync(0xffffffffu, lpA, 2);
    lpB += __shfl_xor_sync(0xffffffffu, lpB, 1);
    lpB += __shfl_xor_sync(0xffffffffu, lpB, 2);
    float invA = 1.0f / lpA, invB = 1.0f / lpB;

    int rA = q0 + 16 * w + gid;
    float* outA = &out[(((size_t)b * L_ + rA) * H_ + h) * D_ + 2 * tig];
    float* outB = &out[(((size_t)b * L_ + rA + 8) * H_ + h) * D_ + 2 * tig];
#pragma unroll
    for (int n = 0; n < 8; n++) {
        *(float2*)(outA + 8 * n) = make_float2(O[n][0] * invA, O[n][1] * invA);
        *(float2*)(outB + 8 * n) = make_float2(O[n][2] * invB, O[n][3] * invB);
    }
}

extern "C" void kernel_launch(void* const* d_in, const int* in_sizes, int n_in,
                              void* d_out, int out_size) {
    const float* qs   = (const float*)d_in[0];
    const float* ks   = (const float*)d_in[1];
    const float* vs   = (const float*)d_in[2];
    const float* qs_s = (const float*)d_in[3];
    const float* ks_s = (const float*)d_in[4];
    const float* a    = (const float*)d_in[5];
    const float* b    = (const float*)d_in[6];
    const float* c    = (const float*)d_in[7];
    float* out = (float*)d_out;

    prep_kernel<<<(B_ * H_ * L_ * D_ / 4 + 255) / 256, 256>>>(
        (const float4*)ks, (const float4*)vs);
    lut_kernel<<<dim3((LUT_N + 128) / 128, H_), 128>>>(a, b, c);

    cudaFuncSetAttribute(attn_kernel,
                         cudaFuncAttributeMaxDynamicSharedMemorySize, SMEM_TOTAL);
    attn_kernel<<<dim3(L_ / 128, H_, B_), 256, SMEM_TOTAL>>>(qs, qs_s, ks_s, out);
}